// round 6
// baseline (speedup 1.0000x reference)
#include <cuda_runtime.h>
#include <math.h>

#define NCH   256
#define PLANE 4096         // 64*64
#define PITCH 68           // smem row pitch (floats): 16B-aligned, 4-row stride = 272 % 32 = 16 banks (conflict-free)
#define SROWS 68           // 64 rows + 2-row halo top/bottom
#define ROFF  2

__device__ __forceinline__ float4 fmax4(float4 a, float4 b) {
    return make_float4(fmaxf(a.x, b.x), fmaxf(a.y, b.y),
                       fmaxf(a.z, b.z), fmaxf(a.w, b.w));
}

__global__ void __launch_bounds__(256, 6)
spp_kernel(const float* __restrict__ x, float* __restrict__ out) {
    __shared__ float s[2][SROWS][PITCH];   // double buffer: pool g uses s[g&1]

    const int tid   = threadIdx.x;
    const int plane = blockIdx.x;          // b*256 + c
    const int batch = plane >> 8;
    const int ch    = plane & 255;

    const float* in = x + (size_t)plane * PLANE;
    float* o0 = out + ((size_t)batch * 4 * NCH + ch) * PLANE;   // group 0 (copy of x)

    // ---- init ONLY the row-halo rows (0,1,66,67) of both buffers to -inf ----
    for (int i = tid; i < 2 * PITCH; i += 256) {
        int r = i / PITCH, c = i % PITCH;
        s[0][r][c]      = -INFINITY;
        s[0][66 + r][c] = -INFINITY;
        s[1][r][c]      = -INFINITY;
        s[1][66 + r][c] = -INFINITY;
    }

    // each thread owns a 4x4 tile
    const int tr = (tid >> 4) << 2;     // tile row base: 0..60
    const int tc = (tid & 15) << 2;     // tile col base: 0..60
    const int ct = tid & 15;            // column tile index (0..15)

    const int base = (tr << 4) + (tc >> 2);   // float4 index of tile origin in a plane

    // ---- load own tile (streaming) + passthrough copy to group 0 ----
    float4 v[4];
    {
        const float4* in4 = (const float4*)in;
        float4*       o4  = (float4*)o0;
        #pragma unroll
        for (int rr = 0; rr < 4; rr++) {
            v[rr] = __ldcs(&in4[base + (rr << 4)]);
            __stcs(&o4[base + (rr << 4)], v[rr]);
        }
    }

    float4* ogp = (float4*)o0 + base;   // walked by +NCH*PLANE/4 per group

    __syncthreads();   // covers halo init

    // three chained window-5 pools: mp5, mp9 = mp5^2, mp13 = mp5^3
    #pragma unroll
    for (int g = 1; g <= 3; g++) {
        const int buf = g & 1;

        // ---- horizontal window-5 max, entirely via warp shuffle ----
        float4 h[4];
        #pragma unroll
        for (int rr = 0; rr < 4; rr++) {
            float4 a = v[rr];
            float lz = __shfl_up_sync(0xFFFFFFFFu, a.z, 1);   // col tc-2
            float lw = __shfl_up_sync(0xFFFFFFFFu, a.w, 1);   // col tc-1
            float rx = __shfl_down_sync(0xFFFFFFFFu, a.x, 1); // col tc+4
            float ry = __shfl_down_sync(0xFFFFFFFFu, a.y, 1); // col tc+5
            if (ct == 0)  { lz = -INFINITY; lw = -INFINITY; } // image left border
            if (ct == 15) { rx = -INFINITY; ry = -INFINITY; } // image right border

            float cyz = fmaxf(a.y, a.z);
            float cxw = fmaxf(a.x, a.w);
            float m4  = fmaxf(cyz, cxw);                 // max(x,y,z,w)
            h[rr].x = fmaxf(fmaxf(lz, lw), fmaxf(a.x, cyz));    // cols tc-2..tc+2
            h[rr].y = fmaxf(lw, m4);                            // cols tc-1..tc+3
            h[rr].z = fmaxf(m4, rx);                            // cols tc  ..tc+4
            h[rr].w = fmaxf(cyz, fmaxf(a.w, fmaxf(rx, ry)));    // cols tc+1..tc+5
        }

        // ---- exchange rows through smem for the vertical halo ----
        #pragma unroll
        for (int rr = 0; rr < 4; rr++)
            *(float4*)&s[buf][tr + rr + ROFF][tc] = h[rr];
        __syncthreads();

        // halo rows: tr-2, tr-1, tr+4, tr+5  (padded indices tr+0, tr+1, tr+6, tr+7)
        float4 um2 = *(const float4*)&s[buf][tr + 0][tc];
        float4 um1 = *(const float4*)&s[buf][tr + 1][tc];
        float4 up4 = *(const float4*)&s[buf][tr + 6][tc];
        float4 up5 = *(const float4*)&s[buf][tr + 7][tc];

        // ---- vertical window-5 max in registers ----
        float4 m12 = fmax4(h[1], h[2]);
        float4 m03 = fmax4(h[0], h[3]);
        float4 m4  = fmax4(m12, m03);
        float4 y0 = fmax4(fmax4(um2, um1), fmax4(h[0], m12));
        float4 y1 = fmax4(um1, m4);
        float4 y2 = fmax4(m4, up4);
        float4 y3 = fmax4(m12, fmax4(h[3], fmax4(up4, up5)));

        // ---- store to output group g (streaming); keep as input for next pool ----
        ogp += NCH * PLANE / 4;
        __stcs(ogp +  0, y0);
        __stcs(ogp + 16, y1);
        __stcs(ogp + 32, y2);
        __stcs(ogp + 48, y3);

        v[0] = y0; v[1] = y1; v[2] = y2; v[3] = y3;
        // no trailing barrier: next write to this smem buffer is two pools away,
        // separated by the other buffer's __syncthreads (WAR-safe)
    }
}

extern "C" void kernel_launch(void* const* d_in, const int* in_sizes, int n_in,
                              void* d_out, int out_size) {
    const float* x = (const float*)d_in[0];
    float* out = (float*)d_out;
    spp_kernel<<<4096, 256>>>(x, out);
}

// round 9
// speedup vs baseline: 1.0439x; 1.0439x over previous
#include <cuda_runtime.h>
#include <math.h>

#define NCH   256
#define PLANE 4096         // 64*64
#define PITCH 68           // smem row pitch (floats): 16B-aligned, 4-row stride = 272 % 32 = 16 banks (conflict-free)
#define SROWS 68           // 64 rows + 2-row halo top/bottom
#define ROFF  2

__device__ __forceinline__ float4 fmax4(float4 a, float4 b) {
    return make_float4(fmaxf(a.x, b.x), fmaxf(a.y, b.y),
                       fmaxf(a.z, b.z), fmaxf(a.w, b.w));
}

__global__ void __launch_bounds__(256)
spp_kernel(const float* __restrict__ x, float* __restrict__ out) {
    __shared__ float s[2][SROWS][PITCH];   // one buffer per plane

    const int tid    = threadIdx.x;
    const int plane0 = blockIdx.x << 1;    // two adjacent channels per block
    const int batch  = plane0 >> 8;
    const int ch0    = plane0 & 255;       // even; ch1 = ch0+1 (same batch, adjacent)

    const float4* in4a = (const float4*)(x + (size_t)plane0 * PLANE);
    const float4* in4b = in4a + PLANE / 4;

    float* o0 = out + ((size_t)batch * 4 * NCH + ch0) * PLANE;  // group-0 base, plane 0

    // ---- init ONLY the row-halo rows (0,1,66,67) of both buffers to -inf ----
    for (int i = tid; i < 2 * PITCH; i += 256) {
        int r = i / PITCH, c = i % PITCH;
        s[0][r][c]      = -INFINITY;
        s[0][66 + r][c] = -INFINITY;
        s[1][r][c]      = -INFINITY;
        s[1][66 + r][c] = -INFINITY;
    }

    // each thread owns a 4x4 tile in each plane
    const int tr = (tid >> 4) << 2;     // tile row base: 0..60
    const int tc = (tid & 15) << 2;     // tile col base: 0..60
    const int ct = tid & 15;            // column tile index (0..15)

    const int base = (tr << 4) + (tc >> 2);   // float4 index of tile origin in a plane

    // ---- load both planes (8 independent LDG.128) + passthrough copy to group 0 ----
    float4 v[2][4];
    #pragma unroll
    for (int rr = 0; rr < 4; rr++) {
        v[0][rr] = in4a[base + (rr << 4)];
        v[1][rr] = in4b[base + (rr << 4)];
    }
    {
        float4* o4a = (float4*)o0;
        float4* o4b = o4a + PLANE / 4;
        #pragma unroll
        for (int rr = 0; rr < 4; rr++) {
            o4a[base + (rr << 4)] = v[0][rr];
            o4b[base + (rr << 4)] = v[1][rr];
        }
    }

    float4* ogp = (float4*)o0 + base;   // walked by +NCH*PLANE/4 per group; +PLANE/4 selects plane 1

    __syncthreads();   // covers halo init

    // three chained window-5 pools: mp5, mp9 = mp5^2, mp13 = mp5^3
    #pragma unroll
    for (int g = 1; g <= 3; g++) {
        // ---- horizontal window-5 max via warp shuffle; overwrite v in place ----
        #pragma unroll
        for (int p = 0; p < 2; p++) {
            #pragma unroll
            for (int rr = 0; rr < 4; rr++) {
                float4 a = v[p][rr];
                float lz = __shfl_up_sync(0xFFFFFFFFu, a.z, 1);   // col tc-2
                float lw = __shfl_up_sync(0xFFFFFFFFu, a.w, 1);   // col tc-1
                float rx = __shfl_down_sync(0xFFFFFFFFu, a.x, 1); // col tc+4
                float ry = __shfl_down_sync(0xFFFFFFFFu, a.y, 1); // col tc+5
                if (ct == 0)  { lz = -INFINITY; lw = -INFINITY; } // image left border
                if (ct == 15) { rx = -INFINITY; ry = -INFINITY; } // image right border

                float cyz = fmaxf(a.y, a.z);
                float cxw = fmaxf(a.x, a.w);
                float m4  = fmaxf(cyz, cxw);                 // max(x,y,z,w)
                float4 h;
                h.x = fmaxf(fmaxf(lz, lw), fmaxf(a.x, cyz));    // cols tc-2..tc+2
                h.y = fmaxf(lw, m4);                            // cols tc-1..tc+3
                h.z = fmaxf(m4, rx);                            // cols tc  ..tc+4
                h.w = fmaxf(cyz, fmaxf(a.w, fmaxf(rx, ry)));    // cols tc+1..tc+5
                v[p][rr] = h;                                   // H result replaces input
                *(float4*)&s[p][tr + rr + ROFF][tc] = h;        // row exchange for V halo
            }
        }
        __syncthreads();

        // ---- vertical window-5 max in registers; store to output group g ----
        #pragma unroll
        for (int p = 0; p < 2; p++) {
            // halo rows: tr-2, tr-1, tr+4, tr+5 (padded indices tr+0, tr+1, tr+6, tr+7)
            float4 um2 = *(const float4*)&s[p][tr + 0][tc];
            float4 um1 = *(const float4*)&s[p][tr + 1][tc];
            float4 up4 = *(const float4*)&s[p][tr + 6][tc];
            float4 up5 = *(const float4*)&s[p][tr + 7][tc];

            float4 m12 = fmax4(v[p][1], v[p][2]);
            float4 m03 = fmax4(v[p][0], v[p][3]);
            float4 m4  = fmax4(m12, m03);
            float4 y0 = fmax4(fmax4(um2, um1), fmax4(v[p][0], m12));
            float4 y1 = fmax4(um1, m4);
            float4 y2 = fmax4(m4, up4);
            float4 y3 = fmax4(m12, fmax4(v[p][3], fmax4(up4, up5)));

            float4* og = ogp + (size_t)g * (NCH * PLANE / 4) + p * (PLANE / 4);
            og[ 0] = y0;
            og[16] = y1;
            og[32] = y2;
            og[48] = y3;

            v[p][0] = y0; v[p][1] = y1; v[p][2] = y2; v[p][3] = y3;
        }
        if (g < 3) __syncthreads();   // WAR: next pool rewrites s
    }
}

extern "C" void kernel_launch(void* const* d_in, const int* in_sizes, int n_in,
                              void* d_out, int out_size) {
    const float* x = (const float*)d_in[0];
    float* out = (float*)d_out;
    // 2048 blocks × 2 planes = 4096 planes
    spp_kernel<<<2048, 256>>>(x, out);
}